// round 9
// baseline (speedup 1.0000x reference)
#include <cuda_runtime.h>

// AdaptiveStdPooling2d: x [B=16, C=128, H=512, W=128] fp32
// kh = 64 (variance over height), kw = 8 (sum of stds over width)
// out [B, C, 8, 16] fp32
//
// One warp per (b,c,ho) slab: 64 rows x 128 cols = 32KB contiguous.
// LDG.E.256 streaming loads (ld.global.cs.v8.f32). Half-warp-per-row:
// lanes 0-15 even rows, 16-31 odd rows; each lane owns one kw=8 column
// group -> merge row-parity partials with shfl_xor(16).
// block=512 (16 warps/CTA, 512KB contiguous per CTA), grid=1024.
//
// R9 change (vs R8): unroll 8 -> 16. Dose-response so far: unroll 4 ->
// 79.2% DRAM, unroll 8 -> 81%. Deeper front-batched load queue per warp
// has been the only knob that moves DRAM%; occupancy changes have been
// irrelevant. launch_bounds(512) leaves ptxas room up to ~128 regs.

#define EPS 1e-14f

__global__ __launch_bounds__(512)
void adaptive_std_pool_kernel(const float* __restrict__ x,
                              float* __restrict__ out) {
    const int warp_global = blockIdx.x * 16 + (threadIdx.x >> 5); // slab id
    const int lane = threadIdx.x & 31;
    const int half = lane >> 4;   // 0: even rows, 1: odd rows
    const int sub  = lane & 15;   // column group (8 cols = 32B)

    const float* __restrict__ base =
        x + (size_t)warp_global * 8192 + (size_t)half * 128 + (size_t)sub * 8;

    float s0=0.f,s1=0.f,s2=0.f,s3=0.f,s4=0.f,s5=0.f,s6=0.f,s7=0.f;
    float q0=0.f,q1=0.f,q2=0.f,q3=0.f,q4=0.f,q5=0.f,q6=0.f,q7=0.f;

#pragma unroll 16
    for (int r = 0; r < 32; ++r) {
        const float* p = base + (size_t)r * 256;  // 2 rows per iter
        float a0,a1,a2,a3,a4,a5,a6,a7;
        asm volatile(
            "ld.global.cs.v8.f32 {%0,%1,%2,%3,%4,%5,%6,%7}, [%8];"
            : "=f"(a0), "=f"(a1), "=f"(a2), "=f"(a3),
              "=f"(a4), "=f"(a5), "=f"(a6), "=f"(a7)
            : "l"(p));
        s0 += a0; q0 = fmaf(a0, a0, q0);
        s1 += a1; q1 = fmaf(a1, a1, q1);
        s2 += a2; q2 = fmaf(a2, a2, q2);
        s3 += a3; q3 = fmaf(a3, a3, q3);
        s4 += a4; q4 = fmaf(a4, a4, q4);
        s5 += a5; q5 = fmaf(a5, a5, q5);
        s6 += a6; q6 = fmaf(a6, a6, q6);
        s7 += a7; q7 = fmaf(a7, a7, q7);
    }

    // merge even-row / odd-row partials across the half-warps
    s0 += __shfl_xor_sync(0xffffffffu, s0, 16);
    s1 += __shfl_xor_sync(0xffffffffu, s1, 16);
    s2 += __shfl_xor_sync(0xffffffffu, s2, 16);
    s3 += __shfl_xor_sync(0xffffffffu, s3, 16);
    s4 += __shfl_xor_sync(0xffffffffu, s4, 16);
    s5 += __shfl_xor_sync(0xffffffffu, s5, 16);
    s6 += __shfl_xor_sync(0xffffffffu, s6, 16);
    s7 += __shfl_xor_sync(0xffffffffu, s7, 16);
    q0 += __shfl_xor_sync(0xffffffffu, q0, 16);
    q1 += __shfl_xor_sync(0xffffffffu, q1, 16);
    q2 += __shfl_xor_sync(0xffffffffu, q2, 16);
    q3 += __shfl_xor_sync(0xffffffffu, q3, 16);
    q4 += __shfl_xor_sync(0xffffffffu, q4, 16);
    q5 += __shfl_xor_sync(0xffffffffu, q5, 16);
    q6 += __shfl_xor_sync(0xffffffffu, q6, 16);
    q7 += __shfl_xor_sync(0xffffffffu, q7, 16);

    if (half == 0) {
        const float inv = 1.0f / 64.0f;
        float ssum = 0.f;
        float m;
        m = s0 * inv; ssum += sqrtf(fmaf(-m, m, q0 * inv) + EPS);
        m = s1 * inv; ssum += sqrtf(fmaf(-m, m, q1 * inv) + EPS);
        m = s2 * inv; ssum += sqrtf(fmaf(-m, m, q2 * inv) + EPS);
        m = s3 * inv; ssum += sqrtf(fmaf(-m, m, q3 * inv) + EPS);
        m = s4 * inv; ssum += sqrtf(fmaf(-m, m, q4 * inv) + EPS);
        m = s5 * inv; ssum += sqrtf(fmaf(-m, m, q5 * inv) + EPS);
        m = s6 * inv; ssum += sqrtf(fmaf(-m, m, q6 * inv) + EPS);
        m = s7 * inv; ssum += sqrtf(fmaf(-m, m, q7 * inv) + EPS);
        out[(size_t)warp_global * 16 + sub] = ssum;
    }
}

extern "C" void kernel_launch(void* const* d_in, const int* in_sizes, int n_in,
                              void* d_out, int out_size) {
    const float* x = (const float*)d_in[0];
    float* out = (float*)d_out;
    // 16384 slabs / 16 warps per CTA = 1024 CTAs x 512 threads
    adaptive_std_pool_kernel<<<1024, 512>>>(x, out);
}

// round 10
// speedup vs baseline: 1.0174x; 1.0174x over previous
#include <cuda_runtime.h>

// AdaptiveStdPooling2d: x [B=16, C=128, H=512, W=128] fp32
// kh = 64 (variance over height), kw = 8 (sum of stds over width)
// out [B, C, 8, 16] fp32
//
// One warp per (b,c,ho) slab: 64 rows x 128 cols = 32KB contiguous.
// LDG.E.256 streaming loads. Half-warp-per-row: lanes 0-15 even rows,
// 16-31 odd rows; each lane owns one kw=8 column group -> merge
// row-parity partials with shfl_xor(16).
// block=512 (16 warps/CTA, 512KB contiguous per CTA), grid=1024 (R8 best).
//
// R10 change (vs R8): load cache op .cs -> .cv. B300_MICROARCH's measured
// full-chip stream ceiling (~6300 B/cyc = 6.9 TB/s @LOCK) was taken with
// LDG.cv; .cv skips allocation entirely where .cs still allocates
// (evict-first) and pays L2 tag+eviction work on 512MB of single-use lines.

#define EPS 1e-14f

__global__ __launch_bounds__(512)
void adaptive_std_pool_kernel(const float* __restrict__ x,
                              float* __restrict__ out) {
    const int warp_global = blockIdx.x * 16 + (threadIdx.x >> 5); // slab id
    const int lane = threadIdx.x & 31;
    const int half = lane >> 4;   // 0: even rows, 1: odd rows
    const int sub  = lane & 15;   // column group (8 cols = 32B)

    const float* __restrict__ base =
        x + (size_t)warp_global * 8192 + (size_t)half * 128 + (size_t)sub * 8;

    float s0=0.f,s1=0.f,s2=0.f,s3=0.f,s4=0.f,s5=0.f,s6=0.f,s7=0.f;
    float q0=0.f,q1=0.f,q2=0.f,q3=0.f,q4=0.f,q5=0.f,q6=0.f,q7=0.f;

#pragma unroll 8
    for (int r = 0; r < 32; ++r) {
        const float* p = base + (size_t)r * 256;  // 2 rows per iter
        float a0,a1,a2,a3,a4,a5,a6,a7;
        asm volatile(
            "ld.global.cv.v8.f32 {%0,%1,%2,%3,%4,%5,%6,%7}, [%8];"
            : "=f"(a0), "=f"(a1), "=f"(a2), "=f"(a3),
              "=f"(a4), "=f"(a5), "=f"(a6), "=f"(a7)
            : "l"(p));
        s0 += a0; q0 = fmaf(a0, a0, q0);
        s1 += a1; q1 = fmaf(a1, a1, q1);
        s2 += a2; q2 = fmaf(a2, a2, q2);
        s3 += a3; q3 = fmaf(a3, a3, q3);
        s4 += a4; q4 = fmaf(a4, a4, q4);
        s5 += a5; q5 = fmaf(a5, a5, q5);
        s6 += a6; q6 = fmaf(a6, a6, q6);
        s7 += a7; q7 = fmaf(a7, a7, q7);
    }

    // merge even-row / odd-row partials across the half-warps
    s0 += __shfl_xor_sync(0xffffffffu, s0, 16);
    s1 += __shfl_xor_sync(0xffffffffu, s1, 16);
    s2 += __shfl_xor_sync(0xffffffffu, s2, 16);
    s3 += __shfl_xor_sync(0xffffffffu, s3, 16);
    s4 += __shfl_xor_sync(0xffffffffu, s4, 16);
    s5 += __shfl_xor_sync(0xffffffffu, s5, 16);
    s6 += __shfl_xor_sync(0xffffffffu, s6, 16);
    s7 += __shfl_xor_sync(0xffffffffu, s7, 16);
    q0 += __shfl_xor_sync(0xffffffffu, q0, 16);
    q1 += __shfl_xor_sync(0xffffffffu, q1, 16);
    q2 += __shfl_xor_sync(0xffffffffu, q2, 16);
    q3 += __shfl_xor_sync(0xffffffffu, q3, 16);
    q4 += __shfl_xor_sync(0xffffffffu, q4, 16);
    q5 += __shfl_xor_sync(0xffffffffu, q5, 16);
    q6 += __shfl_xor_sync(0xffffffffu, q6, 16);
    q7 += __shfl_xor_sync(0xffffffffu, q7, 16);

    if (half == 0) {
        const float inv = 1.0f / 64.0f;
        float ssum = 0.f;
        float m;
        m = s0 * inv; ssum += sqrtf(fmaf(-m, m, q0 * inv) + EPS);
        m = s1 * inv; ssum += sqrtf(fmaf(-m, m, q1 * inv) + EPS);
        m = s2 * inv; ssum += sqrtf(fmaf(-m, m, q2 * inv) + EPS);
        m = s3 * inv; ssum += sqrtf(fmaf(-m, m, q3 * inv) + EPS);
        m = s4 * inv; ssum += sqrtf(fmaf(-m, m, q4 * inv) + EPS);
        m = s5 * inv; ssum += sqrtf(fmaf(-m, m, q5 * inv) + EPS);
        m = s6 * inv; ssum += sqrtf(fmaf(-m, m, q6 * inv) + EPS);
        m = s7 * inv; ssum += sqrtf(fmaf(-m, m, q7 * inv) + EPS);
        out[(size_t)warp_global * 16 + sub] = ssum;
    }
}

extern "C" void kernel_launch(void* const* d_in, const int* in_sizes, int n_in,
                              void* d_out, int out_size) {
    const float* x = (const float*)d_in[0];
    float* out = (float*)d_out;
    // 16384 slabs / 16 warps per CTA = 1024 CTAs x 512 threads
    adaptive_std_pool_kernel<<<1024, 512>>>(x, out);
}